// round 12
// baseline (speedup 1.0000x reference)
#include <cuda_runtime.h>
#include <math.h>

#define B_     16
#define TMAX   4096
#define DMODEL 1024
#define H_     16
#define DH     64
#define NSPLIT 64
#define CHUNK  64    // TMAX / NSPLIT; 8 warps * 8 t

// -------- scratch (device globals; no allocation allowed) --------
__device__ float4 g_tab4[TMAX * 16];                // (c0,s0,c1,s1) per (t, j)
__device__ float  g_qkvp[3 * B_ * H_ * 4 * DH];     // qkv partials over 4 e-chunks
__device__ float  g_pm[B_ * H_ * NSPLIT];           // split max
__device__ float  g_pl[B_ * H_ * NSPLIT];           // split sumexp
__device__ float  g_pacc[B_ * H_ * NSPLIT * DH];    // split weighted V accum
__device__ float  g_outp[4 * B_ * DMODEL];          // out-proj split-k partials

// ================= Stage 1: RoPE table + QKV projection (fused grid) =================
__global__ void k_stage1(const float* __restrict__ x,
                         const float* __restrict__ Wq,
                         const float* __restrict__ Wk,
                         const float* __restrict__ Wv) {
    int tid = threadIdx.x;

    if (blockIdx.x < 512) {
        // RoPE table: fp64 inv_freq -> f32 (ref-matching), f32 angle, fp64
        // multiply-based range reduction, f32 sincos.
        __shared__ float sinv[32];
        if (tid < 32) {
            double invd = exp(-(double)tid * (log(10000.0) / 32.0));
            sinv[tid] = (float)invd;
        }
        __syncthreads();
        int idx = blockIdx.x * 256 + tid;     // 131072 entries
        int t = idx >> 5, i = idx & 31;
        float angf = (float)t * sinv[i];
        double ang = (double)angf;
        const double TWO_PI     = 6.283185307179586476925286766559;
        const double INV_TWO_PI = 0.15915494309189533576888376337251;
        double r = ang - TWO_PI * floor(ang * INV_TWO_PI + 0.5);
        float s, c;
        sincosf((float)r, &s, &c);
        ((float2*)g_tab4)[idx] = make_float2(c, s);
        return;
    }

    // QKV projection (partials over 4 e-chunks)
    int bidx = blockIdx.x - 512;           // 0..191
    int ec = bidx & 3, h = (bidx >> 2) & 15, tz = bidx >> 6;   // 0=q 1=k 2=v
    const float* W = (tz == 0) ? Wq : (tz == 1) ? Wk : Wv;

    __shared__ float xs[256 * 16];         // [e_local][b]
    for (int idx = tid; idx < 256 * 16; idx += 256) {
        int el = idx >> 4, b = idx & 15;
        xs[el * 16 + b] = x[b * DMODEL + ec * 256 + el];
    }
    __syncthreads();

    int d = tid & 63, esub = tid >> 6;
    float acc[16];
#pragma unroll
    for (int b = 0; b < 16; ++b) acc[b] = 0.f;

    const float4* xs4 = (const float4*)xs;
    const float* Wbase = W + ((ec * 256) * H_ + h) * DH + d;
#pragma unroll 4
    for (int ee = 0; ee < 64; ++ee) {
        int el = esub * 64 + ee;
        float w = Wbase[el * (H_ * DH)];
        float4 xa = xs4[el * 4 + 0];
        float4 xb = xs4[el * 4 + 1];
        float4 xc = xs4[el * 4 + 2];
        float4 xd = xs4[el * 4 + 3];
        acc[0]  += xa.x * w;  acc[1]  += xa.y * w;  acc[2]  += xa.z * w;  acc[3]  += xa.w * w;
        acc[4]  += xb.x * w;  acc[5]  += xb.y * w;  acc[6]  += xb.z * w;  acc[7]  += xb.w * w;
        acc[8]  += xc.x * w;  acc[9]  += xc.y * w;  acc[10] += xc.z * w;  acc[11] += xc.w * w;
        acc[12] += xd.x * w;  acc[13] += xd.y * w;  acc[14] += xd.z * w;  acc[15] += xd.w * w;
    }

    __shared__ float sred[4][16 * 64];
#pragma unroll
    for (int b = 0; b < 16; ++b) sred[esub][b * 64 + d] = acc[b];
    __syncthreads();

    for (int idx = tid; idx < 1024; idx += 256) {
        int b = idx >> 6, dd = idx & 63;
        float v = sred[0][idx] + sred[1][idx] + sred[2][idx] + sred[3][idx];
        g_qkvp[(((tz * B_ + b) * H_ + h) * 4 + ec) * DH + dd] = v;
    }
}

__global__ void k_pad() {}   // profiling pad: puts k_attn at captured launch idx

// ================= Attention (split over T, folded-RoPE, float4 path) =================
// Warp = 8 timesteps. 16-lane half 'sub' processes timestep t = tw + 2i + sub;
// lane q (0..15) owns dims 4q..4q+3 (one LDG.128 per row). Score reduce is a
// 4-step butterfly within the 16-lane half. Freq symmetry: table float4
// j0=(2q)&15 serves both d<32 and d>=32 via folded B coefficients.
__global__ void __launch_bounds__(256, 4)
k_attn(const float* __restrict__ ck,
       const float* __restrict__ cv,
       const float* __restrict__ bq,
       const float* __restrict__ bk,
       const float* __restrict__ bv,
       const int*   __restrict__ cip) {
    int bh = blockIdx.x;
    int b = bh >> 4, h = bh & 15;
    int ci = *cip;
    int Tlen = ci + 1;
    int t0 = blockIdx.y * CHUNK;
    int sidx = bh * NSPLIT + blockIdx.y;
    int tid = threadIdx.x;

    if (t0 >= Tlen) {
        if (tid == 0) { g_pm[sidx] = -1e30f; g_pl[sidx] = 0.f; }
        if (tid < DH) g_pacc[sidx * DH + tid] = 0.f;
        return;
    }
    int t1 = min(t0 + CHUNK, Tlen);

    int w = tid >> 5, l = tid & 31;
    int sub = l >> 4, q = l & 15;
    int d0 = 4 * q;

    // ---- setup (warp 0): rotated q, fresh k/v at slot ci -> smem ----
    __shared__ __align__(16) float sqr[64], skci[64], svci[64];
    if (tid < 32) {
        const float* qp = g_qkvp + (((0 * B_ + b) * H_ + h) * 4) * DH;
        float q1 = qp[tid]      + qp[64 + tid]  + qp[128 + tid] + qp[192 + tid] + bq[h * DH + tid];
        float q2 = qp[32 + tid] + qp[96 + tid]  + qp[160 + tid] + qp[224 + tid] + bq[h * DH + 32 + tid];
        float2 qcs = ((const float2*)g_tab4)[ci * 32 + tid];
        sqr[tid]      = q1 * qcs.x - q2 * qcs.y;
        sqr[tid + 32] = q1 * qcs.y + q2 * qcs.x;
        const float* kp = g_qkvp + (((1 * B_ + b) * H_ + h) * 4) * DH;
        skci[tid]      = kp[tid]      + kp[64 + tid] + kp[128 + tid] + kp[192 + tid] + bk[h * DH + tid];
        skci[tid + 32] = kp[32 + tid] + kp[96 + tid] + kp[160 + tid] + kp[224 + tid] + bk[h * DH + 32 + tid];
        const float* vp = g_qkvp + (((2 * B_ + b) * H_ + h) * 4) * DH;
        svci[tid]      = vp[tid]      + vp[64 + tid] + vp[128 + tid] + vp[192 + tid] + bv[h * DH + tid];
        svci[tid + 32] = vp[32 + tid] + vp[96 + tid] + vp[160 + tid] + vp[224 + tid] + bv[h * DH + 32 + tid];
    }
    __syncthreads();

    // folded coefficients: A_d = qrot[d]; B_d = (d<32 ? qrot[d+32] : -qrot[d-32])
    float A0 = sqr[d0], A1 = sqr[d0 + 1], A2 = sqr[d0 + 2], A3 = sqr[d0 + 3];
    float B0, B1, B2, B3;
    if (q < 8) { B0 =  sqr[d0 + 32]; B1 =  sqr[d0 + 33]; B2 =  sqr[d0 + 34]; B3 =  sqr[d0 + 35]; }
    else       { B0 = -sqr[d0 - 32]; B1 = -sqr[d0 - 31]; B2 = -sqr[d0 - 30]; B3 = -sqr[d0 - 29]; }

    int j0 = (2 * q) & 15;               // table float4 index for dims d0,d0+1
    int tw = t0 + w * 8;
    const float* kbase = ck + ((long)b * TMAX + tw) * (H_ * DH) + h * DH + d0;
    const float* vbase = cv + ((long)b * TMAX + tw) * (H_ * DH) + h * DH + d0;

    // ---- pass 1: 4 iterations x 2 concurrent timesteps ----
    float s[4];
#pragma unroll
    for (int i = 0; i < 4; ++i) {
        int t = tw + 2 * i + sub;
        float4 kv = *(const float4*)(kbase + (2 * i + sub) * (H_ * DH));
        if (t == ci) kv = *(const float4*)(skci + d0);
        float4 ca = g_tab4[t * 16 + j0];
        float4 cb = g_tab4[t * 16 + j0 + 1];
        float dd = kv.x * (ca.x * A0 + ca.y * B0)
                 + kv.y * (ca.z * A1 + ca.w * B1)
                 + kv.z * (cb.x * A2 + cb.y * B2)
                 + kv.w * (cb.z * A3 + cb.w * B3);
        dd += __shfl_xor_sync(0xffffffffu, dd, 8);
        dd += __shfl_xor_sync(0xffffffffu, dd, 4);
        dd += __shfl_xor_sync(0xffffffffu, dd, 2);
        dd += __shfl_xor_sync(0xffffffffu, dd, 1);
        s[i] = (t < t1) ? dd * 0.125f : -1e30f;
    }

    // ---- offline softmax (combine the two 16-lane halves) ----
    float m4 = fmaxf(fmaxf(s[0], s[1]), fmaxf(s[2], s[3]));
    float m = fmaxf(m4, __shfl_xor_sync(0xffffffffu, m4, 16));
    float lsum = 0.f;
#pragma unroll
    for (int i = 0; i < 4; ++i) {
        float p = (s[i] > -5e29f) ? __expf(s[i] - m) : 0.f;
        s[i] = p;
        lsum += p;
    }
    lsum += __shfl_xor_sync(0xffffffffu, lsum, 16);

    // ---- pass 2: weighted V ----
    float4 a = make_float4(0.f, 0.f, 0.f, 0.f);
#pragma unroll
    for (int i = 0; i < 4; ++i) {
        int t = tw + 2 * i + sub;
        float4 vv = *(const float4*)(vbase + (2 * i + sub) * (H_ * DH));
        if (t == ci) vv = *(const float4*)(svci + d0);
        a.x += s[i] * vv.x;
        a.y += s[i] * vv.y;
        a.z += s[i] * vv.z;
        a.w += s[i] * vv.w;
    }
    // combine the two halves (same dims, disjoint timesteps)
    a.x += __shfl_xor_sync(0xffffffffu, a.x, 16);
    a.y += __shfl_xor_sync(0xffffffffu, a.y, 16);
    a.z += __shfl_xor_sync(0xffffffffu, a.z, 16);
    a.w += __shfl_xor_sync(0xffffffffu, a.w, 16);

    // ---- block combine over 8 warps ----
    __shared__ float sm[8], sl[8];
    __shared__ __align__(16) float sacc[8][DH];
    if (l == 0) { sm[w] = m; sl[w] = lsum; }
    if (sub == 0) *(float4*)(&sacc[w][d0]) = a;
    __syncthreads();

    if (tid < DH) {
        int d = tid;
        float M = sm[0];
#pragma unroll
        for (int i = 1; i < 8; ++i) M = fmaxf(M, sm[i]);
        float L = 0.f, A = 0.f;
#pragma unroll
        for (int i = 0; i < 8; ++i) {
            float e = __expf(sm[i] - M);
            L += sl[i] * e;
            A += sacc[i][d] * e;
        }
        g_pacc[sidx * DH + d] = A;
        if (d == 0) { g_pm[sidx] = M; g_pl[sidx] = L; }
    }
}

// ================= Fused split-reduction + out-proj pass 1 =================
__global__ void k_redout(const float* __restrict__ Wo) {
    int ec = blockIdx.x, b = blockIdx.y, kc = blockIdx.z;
    int tid = threadIdx.x;
    int hl = tid >> 6;
    int s  = tid & 63;
    int bh = b * H_ + kc * 4 + hl;

    __shared__ float sPm[4][NSPLIT], sE[4][NSPLIT], sLE[4][NSPLIT];
    sPm[hl][s] = g_pm[bh * NSPLIT + s];
    __syncthreads();
    float M = -1e30f;
#pragma unroll 8
    for (int k = 0; k < NSPLIT; ++k) M = fmaxf(M, sPm[hl][k]);
    float e = __expf(sPm[hl][s] - M);
    sE[hl][s]  = e;
    sLE[hl][s] = g_pl[bh * NSPLIT + s] * e;
    __syncthreads();

    int d = s;
    float L = 0.f, A = 0.f;
#pragma unroll 8
    for (int k = 0; k < NSPLIT; ++k) {
        A += g_pacc[(bh * NSPLIT + k) * DH + d] * sE[hl][k];
        L += sLE[hl][k];
    }
    __shared__ float os[256];
    os[tid] = A / L;
    __syncthreads();

    int e2 = ec * 256 + tid;
    const float* Wp = Wo + (kc * 256) * DMODEL + e2;
    float acc = 0.f;
#pragma unroll 16
    for (int hd = 0; hd < 256; ++hd)
        acc += os[hd] * Wp[hd * DMODEL];
    g_outp[(kc * B_ + b) * DMODEL + e2] = acc;
}

// ================= Out-proj pass 2 =================
__global__ void k_out2(const float* __restrict__ bo, float* __restrict__ out) {
    int idx = blockIdx.x * 256 + threadIdx.x;   // b*1024 + e
    float v = bo[idx & (DMODEL - 1)];
#pragma unroll
    for (int kc = 0; kc < 4; ++kc) v += g_outp[kc * (B_ * DMODEL) + idx];
    out[idx] = v;
}

extern "C" void kernel_launch(void* const* d_in, const int* in_sizes, int n_in,
                              void* d_out, int out_size) {
    const float* x   = (const float*)d_in[0];
    const float* cK  = (const float*)d_in[1];
    const float* cV  = (const float*)d_in[2];
    const float* Wq  = (const float*)d_in[3];
    const float* bq  = (const float*)d_in[4];
    const float* Wk  = (const float*)d_in[5];
    const float* bk  = (const float*)d_in[6];
    const float* Wv  = (const float*)d_in[7];
    const float* bv  = (const float*)d_in[8];
    const float* Wo  = (const float*)d_in[9];
    const float* bo  = (const float*)d_in[10];
    const int*   ci  = (const int*)d_in[11];
    float* out = (float*)d_out;

    k_stage1<<<704, 256>>>(x, Wq, Wk, Wv);
    k_pad<<<1, 32>>>();
    k_pad<<<1, 32>>>();
    k_attn<<<dim3(B_ * H_, NSPLIT), 256>>>(cK, cV, bq, bk, bv, ci);
    k_redout<<<dim3(4, B_, 4), 256>>>(Wo);
    k_out2<<<B_ * DMODEL / 256, 256>>>(bo, out);
}